// round 16
// baseline (speedup 1.0000x reference)
#include <cuda_runtime.h>
#include <cuda_fp16.h>
#include <cstdint>
#include <math.h>

#define S_LEN 20
#define U_LEN 256
#define NTOK  5120
#define NC    64
#define CANDN 1024
#define HD    128
#define TOPK  10
#define RHO_C 0.02f
#define VGS   24
#define CHUNK 32
#define NWORK_MAX 224
#define SCAP  64
// k3a smem layout (bytes)
#define OFF_VT   32768
#define OFF_LJ   57344
#define OFF_TOK  65536
#define OFF_LCNT 65664
#define K3_SMEM  65792

// -------- device scratch --------
__device__ float g_vg[(NC * CANDN + 8) * VGS];
__device__ float g_a[NTOK * VGS];
__device__ int   g_cnt[NC];
__device__ int   g_tok[NC * NTOK];
__device__ int2  g_work[NWORK_MAX + 32];
__device__ int   g_nwork;
__device__ unsigned long long g_part[NTOK * 20];   // per-token, per-half top-10 keys

// f32x2 helpers
__device__ __forceinline__ unsigned long long f2mul(unsigned long long a, unsigned long long b) {
    unsigned long long d;
    asm("mul.rn.f32x2 %0, %1, %2;" : "=l"(d) : "l"(a), "l"(b));
    return d;
}
__device__ __forceinline__ unsigned long long f2fma(unsigned long long a, unsigned long long b, unsigned long long c) {
    unsigned long long d;
    asm("fma.rn.f32x2 %0, %1, %2, %3;" : "=l"(d) : "l"(a), "l"(b), "l"(c));
    return d;
}
__device__ __forceinline__ unsigned long long f2add(unsigned long long a, unsigned long long b) {
    unsigned long long d;
    asm("add.rn.f32x2 %0, %1, %2;" : "=l"(d) : "l"(a), "l"(b));
    return d;
}
__device__ __forceinline__ void cp16(unsigned int dst, const void* src) {
    asm volatile("cp.async.cg.shared.global [%0], [%1], 16;" :: "r"(dst), "l"(src));
}
__device__ __forceinline__ float exact_d2(const float* vp,
    ulonglong2 A0, ulonglong2 A1, ulonglong2 A2, ulonglong2 A3, ulonglong2 A4,
    unsigned long long A5) {
    const ulonglong2* vp2 = (const ulonglong2*)vp;
    ulonglong2 q0 = vp2[0], q1 = vp2[1], q2 = vp2[2], q3 = vp2[3], q4 = vp2[4];
    unsigned long long q5 = *(const unsigned long long*)(vp + 20);
    unsigned long long s0 = f2mul(q0.x, A0.x);
    unsigned long long s1 = f2mul(q0.y, A0.y);
    s0 = f2fma(q1.x, A1.x, s0); s1 = f2fma(q1.y, A1.y, s1);
    s0 = f2fma(q2.x, A2.x, s0); s1 = f2fma(q2.y, A2.y, s1);
    s0 = f2fma(q3.x, A3.x, s0); s1 = f2fma(q3.y, A3.y, s1);
    s0 = f2fma(q4.x, A4.x, s0); s1 = f2fma(q4.y, A4.y, s1);
    s0 = f2fma(q5, A5, s0);
    s0 = f2add(s0, s1);
    float lo = __uint_as_float((unsigned)(s0 & 0xffffffffull));
    float hi = __uint_as_float((unsigned)(s0 >> 32));
    return fmaxf(-2.0f * (lo + hi), 1e-12f);
}

// ============ K_mid (unchanged) ============
__global__ void k_mid(const int* __restrict__ x, const int* __restrict__ tslot,
                      const float* __restrict__ vecs, const int* __restrict__ cand,
                      const int* __restrict__ Iarr, const float* __restrict__ te,
                      const float* __restrict__ Wseq1, const float* __restrict__ bseq1,
                      const float* __restrict__ Wseq2, const float* __restrict__ bseq2,
                      const float* __restrict__ Wto1, const float* __restrict__ bto1,
                      const float* __restrict__ Wto2, const float* __restrict__ bto2,
                      const float* __restrict__ Wti1, const float* __restrict__ bti1,
                      const float* __restrict__ Wti2, const float* __restrict__ bti2) {
    __shared__ float sb[6600];
    int b = blockIdx.x, tid = threadIdx.x;

    if (b < 256) {
        float* W1s = sb;
        float* W2s = sb + 800;
        float* tcs = sb + 1600;
        float* b2s = sb + 1664;
        for (int i = tid; i < 800; i += 128) { W1s[i] = Wti1[i]; W2s[i] = Wti2[i]; }
        if (tid < 40) {
            float acc = bti1[tid];
            #pragma unroll
            for (int i = 0; i < 20; i++) acc += te[40 + i] * Wti1[(20 + i) * 40 + tid];
            tcs[tid] = acc;
        }
        if (tid >= 64 && tid < 84) b2s[tid - 64] = bti2[tid - 64];
        __syncthreads();

        int g0 = b * 256 + tid;
        int v0 = cand[g0], v1 = cand[g0 + 128];
        float in0[20], in1[20];
        const float4* p0 = (const float4*)(vecs + (size_t)v0 * 20);
        const float4* p1 = (const float4*)(vecs + (size_t)v1 * 20);
        #pragma unroll
        for (int q = 0; q < 5; q++) {
            float4 f = p0[q];
            in0[4*q] = f.x; in0[4*q+1] = f.y; in0[4*q+2] = f.z; in0[4*q+3] = f.w;
            float4 h = p1[q];
            in1[4*q] = h.x; in1[4*q+1] = h.y; in1[4*q+2] = h.z; in1[4*q+3] = h.w;
        }
        float o0[20], o1[20];
        #pragma unroll
        for (int d = 0; d < 20; d++) { o0[d] = b2s[d]; o1[d] = b2s[d]; }

        #pragma unroll 1
        for (int a4 = 0; a4 < 40; a4 += 4) {
            float4 t4 = *(const float4*)&tcs[a4];
            float ha0 = t4.x, ha1 = t4.y, ha2 = t4.z, ha3 = t4.w;
            float hb0 = t4.x, hb1 = t4.y, hb2 = t4.z, hb3 = t4.w;
            #pragma unroll
            for (int i = 0; i < 20; i++) {
                float4 w = *(const float4*)&W1s[i * 40 + a4];
                float e0 = in0[i], e1 = in1[i];
                ha0 += e0 * w.x; ha1 += e0 * w.y; ha2 += e0 * w.z; ha3 += e0 * w.w;
                hb0 += e1 * w.x; hb1 += e1 * w.y; hb2 += e1 * w.z; hb3 += e1 * w.w;
            }
            ha0 = fmaxf(ha0, 0.f); ha1 = fmaxf(ha1, 0.f); ha2 = fmaxf(ha2, 0.f); ha3 = fmaxf(ha3, 0.f);
            hb0 = fmaxf(hb0, 0.f); hb1 = fmaxf(hb1, 0.f); hb2 = fmaxf(hb2, 0.f); hb3 = fmaxf(hb3, 0.f);
            #pragma unroll
            for (int dq = 0; dq < 20; dq += 4) {
                float4 w0 = *(const float4*)&W2s[(a4 + 0) * 20 + dq];
                float4 w1 = *(const float4*)&W2s[(a4 + 1) * 20 + dq];
                float4 w2 = *(const float4*)&W2s[(a4 + 2) * 20 + dq];
                float4 w3 = *(const float4*)&W2s[(a4 + 3) * 20 + dq];
                o0[dq+0] += ha0*w0.x + ha1*w1.x + ha2*w2.x + ha3*w3.x;
                o0[dq+1] += ha0*w0.y + ha1*w1.y + ha2*w2.y + ha3*w3.y;
                o0[dq+2] += ha0*w0.z + ha1*w1.z + ha2*w2.z + ha3*w3.z;
                o0[dq+3] += ha0*w0.w + ha1*w1.w + ha2*w2.w + ha3*w3.w;
                o1[dq+0] += hb0*w0.x + hb1*w1.x + hb2*w2.x + hb3*w3.x;
                o1[dq+1] += hb0*w0.y + hb1*w1.y + hb2*w2.y + hb3*w3.y;
                o1[dq+2] += hb0*w0.z + hb1*w1.z + hb2*w2.z + hb3*w3.z;
                o1[dq+3] += hb0*w0.w + hb1*w1.w + hb2*w2.w + hb3*w3.w;
            }
        }
        float n0 = 0.0f, n1 = 0.0f;
        float* d0 = g_vg + (size_t)g0 * VGS;
        float* d1 = g_vg + (size_t)(g0 + 128) * VGS;
        #pragma unroll
        for (int d = 0; d < 20; d++) {
            n0 += o0[d] * o0[d]; d0[d] = o0[d];
            n1 += o1[d] * o1[d]; d1[d] = o1[d];
        }
        d0[20] = n0; d0[21] = 1.0f;
        d1[20] = n1; d1[21] = 1.0f;

    } else if (b < 336) {
        float* Ws1 = sb;
        float* Ws2 = sb + 4000;
        float* Wt1 = sb + 4800;
        float* Wt2 = sb + 5600;
        __shared__ float bs1[40], bs2[20], bt2s[20], tcs2[120];
        for (int i = tid; i < 4000; i += 128) Ws1[i] = Wseq1[i];
        for (int i = tid; i < 800; i += 128) { Ws2[i] = Wseq2[i]; Wt1[i] = Wto1[i]; Wt2[i] = Wto2[i]; }
        if (tid < 40) bs1[tid] = bseq1[tid];
        if (tid >= 64 && tid < 84) { bs2[tid - 64] = bseq2[tid - 64]; bt2s[tid - 64] = bto2[tid - 64]; }
        if (tid < 120) {
            int s = tid / 40, a = tid % 40;
            float acc = bto1[a];
            #pragma unroll
            for (int i = 0; i < 20; i++) acc += te[s * 20 + i] * Wto1[(20 + i) * 40 + a];
            tcs2[tid] = acc;
        }
        __syncthreads();

        int pid = (b - 256) * 128 + tid;
        int n = pid >> 1, h = pid & 1;
        int s = n / U_LEN, u = n % U_LEN;
        int hb = h * 20;

        float hs[20];
        #pragma unroll
        for (int a = 0; a < 20; a++) hs[a] = bs1[hb + a];

        float e[20];
        #pragma unroll 1
        for (int p = 0; p < 5; p++) {
            int k = 4 - p;
            int sel = (s < k) ? s : s - k;
            int xid = x[sel * U_LEN + u];
            const float4* vp = (const float4*)(vecs + (size_t)xid * 20);
            #pragma unroll
            for (int q = 0; q < 5; q++) {
                float4 f = vp[q];
                e[4*q] = f.x; e[4*q+1] = f.y; e[4*q+2] = f.z; e[4*q+3] = f.w;
            }
            #pragma unroll
            for (int i = 0; i < 20; i++) {
                float ei = e[i];
                #pragma unroll
                for (int a = 0; a < 20; a++) hs[a] += ei * Ws1[(p * 20 + i) * 40 + hb + a];
            }
        }

        float po[20];
        #pragma unroll
        for (int d = 0; d < 20; d++) po[d] = 0.0f;
        #pragma unroll 4
        for (int a = 0; a < 20; a++) {
            float r = fmaxf(hs[a], 0.0f);
            #pragma unroll
            for (int d = 0; d < 20; d++) po[d] += r * Ws2[(hb + a) * 20 + d];
        }

        int t24 = tslot[n] % 24;
        int seg = (t24 >= 22 || t24 < 6) ? 0 : (t24 < 14 ? 1 : 2);
        float ht[20];
        #pragma unroll
        for (int a = 0; a < 20; a++) ht[a] = tcs2[seg * 40 + hb + a];
        #pragma unroll
        for (int i = 0; i < 20; i++) {
            float ei = e[i];
            #pragma unroll
            for (int a = 0; a < 20; a++) ht[a] += ei * Wt1[i * 40 + hb + a];
        }
        float px[20];
        #pragma unroll
        for (int d = 0; d < 20; d++) px[d] = 0.0f;
        #pragma unroll 4
        for (int a = 0; a < 20; a++) {
            float r = fmaxf(ht[a], 0.0f);
            #pragma unroll
            for (int d = 0; d < 20; d++) px[d] += r * Wt2[(hb + a) * 20 + d];
        }

        float av[20];
        float nrm = 0.0f;
        #pragma unroll
        for (int d = 0; d < 20; d++) {
            float sp = po[d] + __shfl_xor_sync(0xffffffffu, po[d], 1);
            float tp = px[d] + __shfl_xor_sync(0xffffffffu, px[d], 1);
            av[d] = 0.5f * ((sp + bs2[d]) + (tp + bt2s[d]));
            nrm += av[d] * av[d];
        }
        float* dst = g_a + (size_t)n * VGS;
        #pragma unroll
        for (int d = 0; d < 10; d++) dst[hb / 2 + d] = av[hb / 2 + d];
        if (h == 0) { dst[20] = -0.5f; dst[21] = -0.5f * nrm; }

    } else {
        __shared__ int scnt[NC];
        if (tid < NC) scnt[tid] = 0;
        __syncthreads();
        int xv[40];
        #pragma unroll
        for (int q = 0; q < 40; q++) xv[q] = x[tid + 128 * q];
        int cv[40];
        #pragma unroll
        for (int q = 0; q < 40; q++) cv[q] = Iarr[xv[q]];
        #pragma unroll
        for (int q = 0; q < 40; q++) {
            int c = cv[q];
            int p = atomicAdd(&scnt[c], 1);
            g_tok[c * NTOK + p] = tid + 128 * q;
        }
        __syncthreads();
        if (tid < NC) g_cnt[tid] = scnt[tid];
        if (tid == 0) {
            int w = 0;
            for (int c = 0; c < NC; c++) {
                int cnt = scnt[c];
                for (int st = 0; st < cnt; st += CHUNK) g_work[w++] = make_int2(c, st);
            }
            g_nwork = w;
        }
    }
}

// ============ K3a: per-(chunk, candidate-half) exact top-10 ============
// grid (NWORK_MAX, 2), 512 threads. Warp w scans 32 rows of its half.
__global__ void __launch_bounds__(512, 2)
k3a_scan(const int* __restrict__ x, const int* __restrict__ cand,
         float* __restrict__ out_unused) {
    extern __shared__ char smraw[];
    __half* d2h  = (__half*)smraw;                  // [512][32] col-swizzled
    char*   vt_g = smraw + OFF_VT;                  // 16 warps x 2 x 768B
    int*    lj   = (int*)  (smraw + OFF_LJ);
    int*    tok_s= (int*)  (smraw + OFF_TOK);
    int*    lcnt = (int*)  (smraw + OFF_LCNT);

    int bid = blockIdx.x;
    if (bid >= g_nwork) return;
    int half = blockIdx.y;
    int2 wk = g_work[bid];
    int cid = wk.x, start = wk.y;
    int cnt = g_cnt[cid];
    int nIn = min(CHUNK, cnt - start);

    int tid = threadIdx.x, lane = tid & 31, warp = tid >> 5;

    if (tid < CHUNK) {
        tok_s[tid] = g_tok[cid * NTOK + start + min(tid, nIn - 1)];
        lcnt[tid] = 0;
    }
    __syncthreads();

    // ---------------- phase 1: fp16 d2 matrix for this half (512 rows) ----------------
    {
        int t = lane;
        int token = tok_s[t];
        const float* ap = g_a + (size_t)token * VGS;
        const ulonglong2* apv = (const ulonglong2*)ap;
        ulonglong2 A0 = apv[0], A1 = apv[1], A2 = apv[2], A3 = apv[3], A4 = apv[4];
        unsigned long long A5 = *(const unsigned long long*)(ap + 20);

        const float* vg = g_vg + (size_t)(cid * CANDN + half * 512) * VGS;
        int jl0 = warp * 32;
        const char* src = (const char*)(vg + (size_t)jl0 * VGS);
        char* myvt = vt_g + warp * 1536;
        unsigned int vt_s = (unsigned int)__cvta_generic_to_shared(myvt);

        cp16(vt_s + lane * 16, src + lane * 16);
        if (lane < 16) cp16(vt_s + 512 + lane * 16, src + 512 + lane * 16);
        asm volatile("cp.async.commit_group;" ::: "memory");

        #pragma unroll 1
        for (int tile = 0; tile < 4; tile++) {
            int cur = tile & 1;
            if (tile < 3) {
                const char* s2 = src + (tile + 1) * 768;
                unsigned int db = vt_s + (unsigned int)(((tile + 1) & 1) * 768);
                cp16(db + lane * 16, s2 + lane * 16);
                if (lane < 16) cp16(db + 512 + lane * 16, s2 + 512 + lane * 16);
                asm volatile("cp.async.commit_group;" ::: "memory");
                asm volatile("cp.async.wait_group 1;" ::: "memory");
            } else {
                asm volatile("cp.async.wait_group 0;" ::: "memory");
            }
            __syncwarp();

            const float* tp = (const float*)(myvt + cur * 768);
            #pragma unroll
            for (int r = 0; r < 8; r++) {
                float d2 = exact_d2(tp + r * 24, A0, A1, A2, A3, A4, A5);
                int jl = jl0 + tile * 8 + r;
                int tcol = t ^ ((jl >> 1) & 15);
                d2h[jl * 32 + tcol] = __float2half_rn(d2);
            }
            __syncwarp();
        }
    }
    __syncthreads();

    // ---------------- phase 2: warp = token (2 reps); exact per-half top-10 ----------------
    #pragma unroll 1
    for (int rep = 0; rep < 2; rep++) {
        int t = warp + rep * 16;
        int tc = t ^ ((lane >> 1) & 15);

        float mv = 3.4e38f;
        #pragma unroll
        for (int i = 0; i < 16; i++)
            mv = fminf(mv, __half2float(d2h[(i * 32 + lane) * 32 + tc]));

        float cur = mv, tau = 3.4e38f;
        #pragma unroll
        for (int r = 0; r < TOPK; r++) {
            float m = cur;
            #pragma unroll
            for (int off = 16; off; off >>= 1)
                m = fminf(m, __shfl_xor_sync(0xffffffffu, m, off));
            tau = m;
            if (cur == m) cur = 3.4e38f;
        }
        tau = tau * 1.005f + 1e-6f;     // fp16 rounding slack

        if (mv <= tau) {
            #pragma unroll 4
            for (int i = 0; i < 16; i++) {
                float v = __half2float(d2h[(i * 32 + lane) * 32 + tc]);
                if (v <= tau) {
                    int p = atomicAdd(&lcnt[t], 1);
                    if (p < SCAP) lj[t * SCAP + p] = i * 32 + lane;
                }
            }
        }
        __syncwarp();

        int n = min(lcnt[t], SCAP);
        int token_t = tok_s[t];
        const float* ap2 = g_a + (size_t)token_t * VGS;
        const ulonglong2* apv2 = (const ulonglong2*)ap2;
        ulonglong2 B0 = apv2[0], B1 = apv2[1], B2 = apv2[2], B3 = apv2[3], B4 = apv2[4];
        unsigned long long B5 = *(const unsigned long long*)(ap2 + 20);
        const float* vgb = g_vg + (size_t)(cid * CANDN + half * 512) * VGS;

        unsigned long long k0 = 0xFFFFFFFFFFFFFFFFull, k1 = 0xFFFFFFFFFFFFFFFFull;
        if (lane < n) {
            int jl = lj[t * SCAP + lane];
            float d2 = exact_d2(vgb + (size_t)jl * VGS, B0, B1, B2, B3, B4, B5);
            k0 = ((unsigned long long)__float_as_uint(d2) << 32) | (unsigned)(half * 512 + jl);
        }
        if (lane + 32 < n) {
            int jl = lj[t * SCAP + lane + 32];
            float d2 = exact_d2(vgb + (size_t)jl * VGS, B0, B1, B2, B3, B4, B5);
            k1 = ((unsigned long long)__float_as_uint(d2) << 32) | (unsigned)(half * 512 + jl);
        }

        unsigned long long mywin = 0;
        #pragma unroll
        for (int r = 0; r < TOPK; r++) {
            unsigned long long c = (k0 < k1) ? k0 : k1;
            unsigned long long wm = c;
            #pragma unroll
            for (int off = 16; off; off >>= 1) {
                unsigned long long o = __shfl_xor_sync(0xffffffffu, wm, off);
                wm = (o < wm) ? o : wm;
            }
            if (k0 == wm) k0 = 0xFFFFFFFFFFFFFFFFull;
            else if (k1 == wm) k1 = 0xFFFFFFFFFFFFFFFFull;
            if (lane == r) mywin = wm;
        }
        if (lane < TOPK)
            g_part[(size_t)token_t * 20 + half * 10 + lane] = mywin;
    }
}

// ============ K3b: merge halves + softmax + embedding gather (warp per token) ============
__global__ void __launch_bounds__(256, 4)
k3b_merge(const int* __restrict__ x, const int* __restrict__ Iarr,
          const int* __restrict__ cand, const float* __restrict__ Eemb,
          float* __restrict__ out) {
    int lane = threadIdx.x & 31, warp = threadIdx.x >> 5;
    int n = blockIdx.x * 8 + warp;
    if (n >= NTOK) return;

    int xv = x[n];
    int cid = Iarr[xv];

    unsigned long long k0 = (lane < 20) ? g_part[(size_t)n * 20 + lane]
                                        : 0xFFFFFFFFFFFFFFFFull;
    unsigned long long mywin = 0;
    #pragma unroll
    for (int r = 0; r < TOPK; r++) {
        unsigned long long wm = k0;
        #pragma unroll
        for (int off = 16; off; off >>= 1) {
            unsigned long long o = __shfl_xor_sync(0xffffffffu, wm, off);
            wm = (o < wm) ? o : wm;
        }
        if (k0 == wm) k0 = 0xFFFFFFFFFFFFFFFFull;   // keys unique (j embedded)
        if (lane == r) mywin = wm;
    }

    float e = 0.0f; int ci = 0;
    if (lane < TOPK) {
        float d2 = __uint_as_float((unsigned)(mywin >> 32));
        int j = (int)(mywin & 0xffffffffu);
        float sc = expf(-RHO_C * sqrtf(d2));
        e = expf(sc - 1.0f);
        ci = cand[cid * CANDN + j];
    } else if (lane == TOPK) {
        e = 1.0f;
        ci = xv;
    }
    float ep = e;
    #pragma unroll
    for (int off = 16; off; off >>= 1) ep += __shfl_xor_sync(0xffffffffu, ep, off);
    float w = e / ep;

    float4 a0 = make_float4(0.f, 0.f, 0.f, 0.f);
    #pragma unroll
    for (int kk = 0; kk < 11; kk++) {
        float wk = __shfl_sync(0xffffffffu, w, kk);
        int   ck = __shfl_sync(0xffffffffu, ci, kk);
        float4 e0 = ((const float4*)(Eemb + (size_t)ck * HD))[lane];
        a0.x += wk * e0.x; a0.y += wk * e0.y; a0.z += wk * e0.z; a0.w += wk * e0.w;
    }
    ((float4*)(out + (size_t)n * HD))[lane] = a0;
}

// ============ launch ============
extern "C" void kernel_launch(void* const* d_in, const int* in_sizes, int n_in,
                              void* d_out, int out_size) {
    const int*   x     = (const int*)  d_in[0];
    const int*   tslot = (const int*)  d_in[1];
    const float* vecs  = (const float*)d_in[2];
    const float* Eemb  = (const float*)d_in[3];
    const int*   Iarr  = (const int*)  d_in[4];
    const int*   cand  = (const int*)  d_in[5];
    const float* te    = (const float*)d_in[6];
    const float* Wseq1 = (const float*)d_in[7];
    const float* bseq1 = (const float*)d_in[8];
    const float* Wseq2 = (const float*)d_in[9];
    const float* bseq2 = (const float*)d_in[10];
    const float* Wto1  = (const float*)d_in[11];
    const float* bto1  = (const float*)d_in[12];
    const float* Wto2  = (const float*)d_in[13];
    const float* bto2  = (const float*)d_in[14];
    const float* Wti1  = (const float*)d_in[15];
    const float* bti1  = (const float*)d_in[16];
    const float* Wti2  = (const float*)d_in[17];
    const float* bti2  = (const float*)d_in[18];
    float* out = (float*)d_out;

    cudaFuncSetAttribute(k3a_scan, cudaFuncAttributeMaxDynamicSharedMemorySize, K3_SMEM);

    k_mid<<<337, 128>>>(x, tslot, vecs, cand, Iarr, te,
                        Wseq1, bseq1, Wseq2, bseq2,
                        Wto1, bto1, Wto2, bto2,
                        Wti1, bti1, Wti2, bti2);
    k3a_scan<<<dim3(NWORK_MAX, 2), 512, K3_SMEM>>>(x, cand, out);
    k3b_merge<<<(NTOK + 7) / 8, 256>>>(x, Iarr, cand, Eemb, out);
}

// round 17
// speedup vs baseline: 1.1034x; 1.1034x over previous
#include <cuda_runtime.h>
#include <cstdint>
#include <math.h>

#define S_LEN 20
#define U_LEN 256
#define NTOK  5120
#define NC    64
#define CANDN 1024
#define HD    128
#define TOPK  10
#define RHO_C 0.02f
#define VGS   24
#define CHUNK 16
#define NWORK_MAX 384
#define D2STR 1025
#define SCAP  64
// k3 smem layout (bytes)
#define OFF_LV   65600
#define OFF_LJ   69696
#define OFF_SW   73792
#define OFF_SI   74560
#define OFF_TOK  75328
#define OFF_LCNT 75392
#define K3_SMEM  75456

// -------- device scratch (g_vg padded: prefetch overrun target) --------
__device__ float g_vg[(NC * CANDN + 8) * VGS];
__device__ float g_a[NTOK * VGS];
__device__ int   g_cnt[NC];
__device__ int   g_tok[NC * NTOK];
__device__ int2  g_work[NWORK_MAX + 32];
__device__ int   g_nwork;

// f32x2 helpers
__device__ __forceinline__ unsigned long long f2mul(unsigned long long a, unsigned long long b) {
    unsigned long long d;
    asm("mul.rn.f32x2 %0, %1, %2;" : "=l"(d) : "l"(a), "l"(b));
    return d;
}
__device__ __forceinline__ unsigned long long f2fma(unsigned long long a, unsigned long long b, unsigned long long c) {
    unsigned long long d;
    asm("fma.rn.f32x2 %0, %1, %2, %3;" : "=l"(d) : "l"(a), "l"(b), "l"(c));
    return d;
}
__device__ __forceinline__ unsigned long long f2add(unsigned long long a, unsigned long long b) {
    unsigned long long d;
    asm("add.rn.f32x2 %0, %1, %2;" : "=l"(d) : "l"(a), "l"(b));
    return d;
}

// ============ K_mid: cand MLP 1 row/thread (0..511) | token MLP (512..591) | bucket (592) ============
__global__ void k_mid(const int* __restrict__ x, const int* __restrict__ tslot,
                      const float* __restrict__ vecs, const int* __restrict__ cand,
                      const int* __restrict__ Iarr, const float* __restrict__ te,
                      const float* __restrict__ Wseq1, const float* __restrict__ bseq1,
                      const float* __restrict__ Wseq2, const float* __restrict__ bseq2,
                      const float* __restrict__ Wto1, const float* __restrict__ bto1,
                      const float* __restrict__ Wto2, const float* __restrict__ bto2,
                      const float* __restrict__ Wti1, const float* __restrict__ bti1,
                      const float* __restrict__ Wti2, const float* __restrict__ bti2) {
    __shared__ float sb[6600];
    int b = blockIdx.x, tid = threadIdx.x;

    if (b < 512) {
        // ---- candidate-side MLP: 1 row/thread, float4 weight loads ----
        float* W1s = sb;            // 800
        float* W2s = sb + 800;      // 800
        float* tcs = sb + 1600;     // 40 (16B aligned)
        float* b2s = sb + 1664;     // 20
        for (int i = tid; i < 800; i += 128) { W1s[i] = Wti1[i]; W2s[i] = Wti2[i]; }
        if (tid < 40) {
            float acc = bti1[tid];
            #pragma unroll
            for (int i = 0; i < 20; i++) acc += te[40 + i] * Wti1[(20 + i) * 40 + tid];
            tcs[tid] = acc;
        }
        if (tid >= 64 && tid < 84) b2s[tid - 64] = bti2[tid - 64];
        __syncthreads();

        int g = b * 128 + tid;
        int v = cand[g];
        float in[20];
        const float4* p0 = (const float4*)(vecs + (size_t)v * 20);
        #pragma unroll
        for (int q = 0; q < 5; q++) {
            float4 f = p0[q];
            in[4*q] = f.x; in[4*q+1] = f.y; in[4*q+2] = f.z; in[4*q+3] = f.w;
        }
        float o[20];
        #pragma unroll
        for (int d = 0; d < 20; d++) o[d] = b2s[d];

        #pragma unroll 1
        for (int a4 = 0; a4 < 40; a4 += 4) {
            float4 t4 = *(const float4*)&tcs[a4];
            float h0 = t4.x, h1 = t4.y, h2 = t4.z, h3 = t4.w;
            #pragma unroll
            for (int i = 0; i < 20; i++) {
                float4 w = *(const float4*)&W1s[i * 40 + a4];
                float e0 = in[i];
                h0 += e0 * w.x; h1 += e0 * w.y; h2 += e0 * w.z; h3 += e0 * w.w;
            }
            h0 = fmaxf(h0, 0.f); h1 = fmaxf(h1, 0.f); h2 = fmaxf(h2, 0.f); h3 = fmaxf(h3, 0.f);
            #pragma unroll
            for (int dq = 0; dq < 20; dq += 4) {
                float4 w0 = *(const float4*)&W2s[(a4 + 0) * 20 + dq];
                float4 w1 = *(const float4*)&W2s[(a4 + 1) * 20 + dq];
                float4 w2 = *(const float4*)&W2s[(a4 + 2) * 20 + dq];
                float4 w3 = *(const float4*)&W2s[(a4 + 3) * 20 + dq];
                o[dq+0] += h0*w0.x + h1*w1.x + h2*w2.x + h3*w3.x;
                o[dq+1] += h0*w0.y + h1*w1.y + h2*w2.y + h3*w3.y;
                o[dq+2] += h0*w0.z + h1*w1.z + h2*w2.z + h3*w3.z;
                o[dq+3] += h0*w0.w + h1*w1.w + h2*w2.w + h3*w3.w;
            }
        }
        float nrm = 0.0f;
        float* dst = g_vg + (size_t)g * VGS;
        #pragma unroll
        for (int d = 0; d < 20; d++) { nrm += o[d] * o[d]; dst[d] = o[d]; }
        dst[20] = nrm;
        dst[21] = 1.0f;

    } else if (b < 592) {
        // ---- token MLP, 2 threads/token ----
        float* Ws1 = sb;
        float* Ws2 = sb + 4000;
        float* Wt1 = sb + 4800;
        float* Wt2 = sb + 5600;
        __shared__ float bs1[40], bs2[20], bt2s[20], tcs2[120];
        for (int i = tid; i < 4000; i += 128) Ws1[i] = Wseq1[i];
        for (int i = tid; i < 800; i += 128) { Ws2[i] = Wseq2[i]; Wt1[i] = Wto1[i]; Wt2[i] = Wto2[i]; }
        if (tid < 40) bs1[tid] = bseq1[tid];
        if (tid >= 64 && tid < 84) { bs2[tid - 64] = bseq2[tid - 64]; bt2s[tid - 64] = bto2[tid - 64]; }
        if (tid < 120) {
            int s = tid / 40, a = tid % 40;
            float acc = bto1[a];
            #pragma unroll
            for (int i = 0; i < 20; i++) acc += te[s * 20 + i] * Wto1[(20 + i) * 40 + a];
            tcs2[tid] = acc;
        }
        __syncthreads();

        int pid = (b - 512) * 128 + tid;
        int n = pid >> 1, h = pid & 1;
        int s = n / U_LEN, u = n % U_LEN;
        int hb = h * 20;

        float hs[20];
        #pragma unroll
        for (int a = 0; a < 20; a++) hs[a] = bs1[hb + a];

        float e[20];
        #pragma unroll 1
        for (int p = 0; p < 5; p++) {
            int k = 4 - p;
            int sel = (s < k) ? s : s - k;
            int xid = x[sel * U_LEN + u];
            const float4* vp = (const float4*)(vecs + (size_t)xid * 20);
            #pragma unroll
            for (int q = 0; q < 5; q++) {
                float4 f = vp[q];
                e[4*q] = f.x; e[4*q+1] = f.y; e[4*q+2] = f.z; e[4*q+3] = f.w;
            }
            #pragma unroll
            for (int i = 0; i < 20; i++) {
                float ei = e[i];
                #pragma unroll
                for (int a = 0; a < 20; a++) hs[a] += ei * Ws1[(p * 20 + i) * 40 + hb + a];
            }
        }

        float po[20];
        #pragma unroll
        for (int d = 0; d < 20; d++) po[d] = 0.0f;
        #pragma unroll 4
        for (int a = 0; a < 20; a++) {
            float r = fmaxf(hs[a], 0.0f);
            #pragma unroll
            for (int d = 0; d < 20; d++) po[d] += r * Ws2[(hb + a) * 20 + d];
        }

        int t24 = tslot[n] % 24;
        int seg = (t24 >= 22 || t24 < 6) ? 0 : (t24 < 14 ? 1 : 2);
        float ht[20];
        #pragma unroll
        for (int a = 0; a < 20; a++) ht[a] = tcs2[seg * 40 + hb + a];
        #pragma unroll
        for (int i = 0; i < 20; i++) {
            float ei = e[i];
            #pragma unroll
            for (int a = 0; a < 20; a++) ht[a] += ei * Wt1[i * 40 + hb + a];
        }
        float px[20];
        #pragma unroll
        for (int d = 0; d < 20; d++) px[d] = 0.0f;
        #pragma unroll 4
        for (int a = 0; a < 20; a++) {
            float r = fmaxf(ht[a], 0.0f);
            #pragma unroll
            for (int d = 0; d < 20; d++) px[d] += r * Wt2[(hb + a) * 20 + d];
        }

        float av[20];
        float nrm = 0.0f;
        #pragma unroll
        for (int d = 0; d < 20; d++) {
            float sp = po[d] + __shfl_xor_sync(0xffffffffu, po[d], 1);
            float tp = px[d] + __shfl_xor_sync(0xffffffffu, px[d], 1);
            av[d] = 0.5f * ((sp + bs2[d]) + (tp + bt2s[d]));
            nrm += av[d] * av[d];
        }
        float* dst = g_a + (size_t)n * VGS;
        #pragma unroll
        for (int d = 0; d < 10; d++) dst[hb / 2 + d] = av[hb / 2 + d];
        if (h == 0) { dst[20] = -0.5f; dst[21] = -0.5f * nrm; }

    } else {
        // ---- bucket + worklist ----
        __shared__ int scnt[NC];
        if (tid < NC) scnt[tid] = 0;
        __syncthreads();
        int xv[40];
        #pragma unroll
        for (int q = 0; q < 40; q++) xv[q] = x[tid + 128 * q];
        int cv[40];
        #pragma unroll
        for (int q = 0; q < 40; q++) cv[q] = Iarr[xv[q]];
        #pragma unroll
        for (int q = 0; q < 40; q++) {
            int c = cv[q];
            int p = atomicAdd(&scnt[c], 1);
            g_tok[c * NTOK + p] = tid + 128 * q;
        }
        __syncthreads();
        if (tid < NC) g_cnt[tid] = scnt[tid];
        if (tid == 0) {
            int w = 0;
            for (int c = 0; c < NC; c++) {
                int cnt = scnt[c];
                for (int st = 0; st < cnt; st += CHUNK) g_work[w++] = make_int2(c, st);
            }
            g_nwork = w;
        }
    }
}

// ============ K3 (R11 verbatim): prefetched d2 matrix + tau-filtered exact top-10 ============
__global__ void __launch_bounds__(256, 3)
k3_score(const int* __restrict__ x, const int* __restrict__ cand,
         const float* __restrict__ Eemb, float* __restrict__ out) {
    extern __shared__ char smraw[];
    float* d2mat = (float*)smraw;
    float* lv    = (float*)(smraw + OFF_LV);
    int*   lj    = (int*)  (smraw + OFF_LJ);
    float* sw_s  = (float*)(smraw + OFF_SW);
    int*   si_s  = (int*)  (smraw + OFF_SI);
    int*   tok_s = (int*)  (smraw + OFF_TOK);
    int*   lcnt  = (int*)  (smraw + OFF_LCNT);

    int bid = blockIdx.x;
    if (bid >= g_nwork) return;
    int2 wk = g_work[bid];
    int cid = wk.x, start = wk.y;
    int cnt = g_cnt[cid];
    int nIn = min(CHUNK, cnt - start);

    int tid = threadIdx.x, lane = tid & 31, warp = tid >> 5;

    if (tid < CHUNK) {
        tok_s[tid] = g_tok[cid * NTOK + start + min(tid, nIn - 1)];
        lcnt[tid] = 0;
    }
    __syncthreads();

    // ---------------- phase 1: d2 matrix with double-buffered prefetch ----------------
    {
        int tl = lane & 15;
        int half = lane >> 4;
        int token = tok_s[tl];

        const float* ap = g_a + (size_t)token * VGS;
        const ulonglong2* apv = (const ulonglong2*)ap;
        ulonglong2 A0 = apv[0], A1 = apv[1], A2 = apv[2], A3 = apv[3], A4 = apv[4];
        unsigned long long A5 = *(const unsigned long long*)(ap + 20);

        const float* vg = g_vg + (size_t)(cid * CANDN) * VGS;
        int j0 = warp * 128 + half * 64;
        float* drow = d2mat + tl * D2STR + j0;

        const float* vp = vg + (size_t)j0 * VGS;
        ulonglong2 q0 = ((const ulonglong2*)vp)[0];
        ulonglong2 q1 = ((const ulonglong2*)vp)[1];
        ulonglong2 q2 = ((const ulonglong2*)vp)[2];
        ulonglong2 q3 = ((const ulonglong2*)vp)[3];
        ulonglong2 q4 = ((const ulonglong2*)vp)[4];
        unsigned long long q5 = *(const unsigned long long*)(vp + 20);

        #pragma unroll 4
        for (int jj = 0; jj < 64; jj++) {
            const float* np = vp + VGS;     // g_vg padded: overrun safe
            ulonglong2 n0 = ((const ulonglong2*)np)[0];
            ulonglong2 n1 = ((const ulonglong2*)np)[1];
            ulonglong2 n2 = ((const ulonglong2*)np)[2];
            ulonglong2 n3 = ((const ulonglong2*)np)[3];
            ulonglong2 n4 = ((const ulonglong2*)np)[4];
            unsigned long long n5 = *(const unsigned long long*)(np + 20);

            unsigned long long s0 = f2mul(q0.x, A0.x);
            unsigned long long s1 = f2mul(q0.y, A0.y);
            s0 = f2fma(q1.x, A1.x, s0); s1 = f2fma(q1.y, A1.y, s1);
            s0 = f2fma(q2.x, A2.x, s0); s1 = f2fma(q2.y, A2.y, s1);
            s0 = f2fma(q3.x, A3.x, s0); s1 = f2fma(q3.y, A3.y, s1);
            s0 = f2fma(q4.x, A4.x, s0); s1 = f2fma(q4.y, A4.y, s1);
            s0 = f2fma(q5, A5, s0);
            s0 = f2add(s0, s1);
            float lo = __uint_as_float((unsigned)(s0 & 0xffffffffull));
            float hi = __uint_as_float((unsigned)(s0 >> 32));
            drow[jj] = fmaxf(-2.0f * (lo + hi), 1e-12f);

            q0 = n0; q1 = n1; q2 = n2; q3 = n3; q4 = n4; q5 = n5;
            vp = np;
        }
    }
    __syncthreads();

    // ---------------- phase 2: per-token selection (warp = token, 2 reps) ----------------
    #pragma unroll 1
    for (int rep = 0; rep < 2; rep++) {
        int t = warp + rep * 8;
        const float* row = d2mat + t * D2STR;

        float mv = 3.4e38f;
        #pragma unroll
        for (int i = 0; i < 32; i++) mv = fminf(mv, row[i * 32 + lane]);

        float cur = mv, tau = 3.4e38f;
        #pragma unroll
        for (int r = 0; r < TOPK; r++) {
            float m = cur;
            #pragma unroll
            for (int off = 16; off; off >>= 1)
                m = fminf(m, __shfl_xor_sync(0xffffffffu, m, off));
            tau = m;
            if (cur == m) cur = 3.4e38f;
        }

        if (mv <= tau) {
            #pragma unroll 4
            for (int i = 0; i < 32; i++) {
                float v = row[i * 32 + lane];
                if (v <= tau) {
                    int p = atomicAdd(&lcnt[t], 1);
                    if (p < SCAP) { lv[t * SCAP + p] = v; lj[t * SCAP + p] = i * 32 + lane; }
                }
            }
        }
        __syncwarp();

        int n = min(lcnt[t], SCAP);
        unsigned long long k0 = 0xFFFFFFFFFFFFFFFFull, k1 = 0xFFFFFFFFFFFFFFFFull;
        if (lane < n)
            k0 = ((unsigned long long)__float_as_uint(lv[t * SCAP + lane]) << 32)
               | (unsigned)lj[t * SCAP + lane];
        if (lane + 32 < n)
            k1 = ((unsigned long long)__float_as_uint(lv[t * SCAP + lane + 32]) << 32)
               | (unsigned)lj[t * SCAP + lane + 32];

        unsigned long long mywin = 0;
        #pragma unroll
        for (int r = 0; r < TOPK; r++) {
            unsigned long long c = (k0 < k1) ? k0 : k1;
            unsigned long long wm = c;
            #pragma unroll
            for (int off = 16; off; off >>= 1) {
                unsigned long long o = __shfl_xor_sync(0xffffffffu, wm, off);
                wm = (o < wm) ? o : wm;
            }
            if (k0 == wm) k0 = 0xFFFFFFFFFFFFFFFFull;
            else if (k1 == wm) k1 = 0xFFFFFFFFFFFFFFFFull;
            if (lane == r) mywin = wm;
        }

        float e = 0.0f; int ci = 0;
        if (lane < TOPK) {
            float d2 = __uint_as_float((unsigned)(mywin >> 32));
            int j = (int)(mywin & 0xffffffffu);
            float sc = expf(-RHO_C * sqrtf(d2));
            e = expf(sc - 1.0f);
            ci = cand[cid * CANDN + j];
        } else if (lane == TOPK) {
            e = 1.0f;
            ci = x[tok_s[t]];
        }
        float ep = e;
        #pragma unroll
        for (int off = 16; off; off >>= 1) ep += __shfl_xor_sync(0xffffffffu, ep, off);
        float inv = 1.0f / ep;
        if (lane <= TOPK) { sw_s[t * 12 + lane] = e * inv; si_s[t * 12 + lane] = ci; }
    }
    __syncthreads();

    // ---------------- epilogue: weighted embedding gather (warp per token, 2 reps) ----------------
    #pragma unroll 1
    for (int rep = 0; rep < 2; rep++) {
        int t = warp + rep * 8;
        if (t < nIn) {
            int token2 = tok_s[t];
            float4 a0 = make_float4(0.f, 0.f, 0.f, 0.f);
            #pragma unroll
            for (int kk = 0; kk < 11; kk++) {
                float w = sw_s[t * 12 + kk];
                float4 e0 = ((const float4*)(Eemb + (size_t)si_s[t * 12 + kk] * HD))[lane];
                a0.x += w * e0.x; a0.y += w * e0.y; a0.z += w * e0.z; a0.w += w * e0.w;
            }
            ((float4*)(out + (size_t)token2 * HD))[lane] = a0;
        }
    }
}

// ============ launch ============
extern "C" void kernel_launch(void* const* d_in, const int* in_sizes, int n_in,
                              void* d_out, int out_size) {
    const int*   x     = (const int*)  d_in[0];
    const int*   tslot = (const int*)  d_in[1];
    const float* vecs  = (const float*)d_in[2];
    const float* Eemb  = (const float*)d_in[3];
    const int*   Iarr  = (const int*)  d_in[4];
    const int*   cand  = (const int*)  d_in[5];
    const float* te    = (const float*)d_in[6];
    const float* Wseq1 = (const float*)d_in[7];
    const float* bseq1 = (const float*)d_in[8];
    const float* Wseq2 = (const float*)d_in[9];
    const float* bseq2 = (const float*)d_in[10];
    const float* Wto1  = (const float*)d_in[11];
    const float* bto1  = (const float*)d_in[12];
    const float* Wto2  = (const float*)d_in[13];
    const float* bto2  = (const float*)d_in[14];
    const float* Wti1  = (const float*)d_in[15];
    const float* bti1  = (const float*)d_in[16];
    const float* Wti2  = (const float*)d_in[17];
    const float* bti2  = (const float*)d_in[18];
    float* out = (float*)d_out;

    cudaFuncSetAttribute(k3_score, cudaFuncAttributeMaxDynamicSharedMemorySize, K3_SMEM);

    k_mid<<<593, 128>>>(x, tslot, vecs, cand, Iarr, te,
                        Wseq1, bseq1, Wseq2, bseq2,
                        Wto1, bto1, Wto2, bto2,
                        Wti1, bti1, Wti2, bti2);
    k3_score<<<NWORK_MAX, 256, K3_SMEM>>>(x, cand, Eemb, out);
}